// round 1
// baseline (speedup 1.0000x reference)
#include <cuda_runtime.h>
#include <float.h>
#include <math.h>

// Problem constants (from reference)
#define BEV_N   200          // BEV_H == BEV_W == 200
#define IMG_H   128
#define IMG_W   352
#define NCH     32
#define NB      2            // batch
#define NCAM    6            // cameras per batch
#define BNMAT   (NB*NCAM)    // 12 projection matrices

// Per-camera reduced projection: rows 0..2 of P=K@RT, columns {0(y),1(x),3(const)}
// (z column unused since plane z == 0)
__device__ float g_P[BNMAT][9];

__global__ void precompute_P_kernel(const float* __restrict__ Ks,
                                    const float* __restrict__ RTs) {
    int m = threadIdx.x;
    if (m >= BNMAT) return;
    const float* K  = Ks  + m * 16;
    const float* RT = RTs + m * 16;
    #pragma unroll
    for (int r = 0; r < 3; r++) {
        #pragma unroll
        for (int ci = 0; ci < 3; ci++) {
            int c = (ci == 2) ? 3 : ci;
            float s = 0.0f;
            #pragma unroll
            for (int k = 0; k < 4; k++)
                s += K[r * 4 + k] * RT[k * 4 + c];
            g_P[m][r * 3 + ci] = s;
        }
    }
}

// One warp per BEV cell (b,i,j); lane == channel. All control flow warp-uniform.
__global__ __launch_bounds__(256) void ipm_kernel(const float* __restrict__ images,
                                                  float* __restrict__ out) {
    const int warp = (blockIdx.x * blockDim.x + threadIdx.x) >> 5;
    const int lane = threadIdx.x & 31;
    const int NCELL = NB * BEV_N * BEV_N;
    if (warp >= NCELL) return;

    const int b   = warp / (BEV_N * BEV_N);
    const int rem = warp - b * (BEV_N * BEV_N);
    const int i   = rem / BEV_N;
    const int j   = rem - i * BEV_N;

    // linspace(-50, 50, 200): match numpy's float64 evaluation, then round to fp32
    const float y = (float)(-50.0 + (double)i * (100.0 / 199.0));
    const float x = (float)(-50.0 + (double)j * (100.0 / 199.0));

    float best = -FLT_MAX;

    #pragma unroll
    for (int cam = 0; cam < NCAM; cam++) {
        const int bn = b * NCAM + cam;
        const float* P = g_P[bn];
        const float pc0 = P[0] * y + P[1] * x + P[2];
        const float pc1 = P[3] * y + P[4] * x + P[5];
        const float pc2 = P[6] * y + P[7] * x + P[8];
        const float inv = 1.0f / (pc2 + 1e-7f);
        const float fx = pc0 * inv;
        const float fy = pc1 * inv;

        float v = 0.0f;
        // Outside [0, W-1) x [0, H-1): clamped bilinear collapses => exactly 0
        if (fx >= 0.0f && fx < (float)(IMG_W - 1) &&
            fy >= 0.0f && fy < (float)(IMG_H - 1)) {
            const float x0f = floorf(fx);
            const float y0f = floorf(fy);
            const int x0 = (int)x0f;
            const int y0 = (int)y0f;
            const float wx1 = fx - x0f, wx0 = 1.0f - wx1;
            const float wy1 = fy - y0f, wy0 = 1.0f - wy1;

            const float* base = images
                + (((size_t)bn * IMG_H + y0) * IMG_W + x0) * NCH + lane;
            const float v00 = __ldg(base);
            const float v10 = __ldg(base + NCH);
            const float v01 = __ldg(base + (size_t)IMG_W * NCH);
            const float v11 = __ldg(base + (size_t)IMG_W * NCH + NCH);

            v = wx0 * wy0 * v00 + wx0 * wy1 * v01
              + wx1 * wy0 * v10 + wx1 * wy1 * v11;
        }
        best = fmaxf(best, v);
    }

    out[(size_t)warp * NCH + lane] = best;
}

extern "C" void kernel_launch(void* const* d_in, const int* in_sizes, int n_in,
                              void* d_out, int out_size) {
    const float* images = (const float*)d_in[0];
    const float* Ks     = (const float*)d_in[1];
    const float* RTs    = (const float*)d_in[2];
    float* out = (float*)d_out;

    precompute_P_kernel<<<1, BNMAT>>>(Ks, RTs);

    const int ncell = NB * BEV_N * BEV_N;        // 80,000 warps
    const int warps_per_block = 8;               // 256 threads
    const int nblocks = (ncell + warps_per_block - 1) / warps_per_block;
    ipm_kernel<<<nblocks, warps_per_block * 32>>>(images, out);
}

// round 2
// speedup vs baseline: 1.0060x; 1.0060x over previous
#include <cuda_runtime.h>
#include <float.h>
#include <math.h>

// Problem constants (from reference)
#define BEV_N   200          // BEV_H == BEV_W == 200
#define IMG_H   128
#define IMG_W   352
#define NCH     32
#define NB      2            // batch
#define NCAM    6            // cameras per batch
#define BNMAT   (NB*NCAM)    // 12 projection matrices

// Per-camera reduced projection: rows 0..2 of P=K@RT, columns {0(y),1(x),3(const)}
// (z column unused since plane z == 0)
__device__ float g_P[BNMAT][9];

__global__ void precompute_P_kernel(const float* __restrict__ Ks,
                                    const float* __restrict__ RTs) {
    int m = threadIdx.x;
    if (m >= BNMAT) return;
    const float* K  = Ks  + m * 16;
    const float* RT = RTs + m * 16;
    #pragma unroll
    for (int r = 0; r < 3; r++) {
        #pragma unroll
        for (int ci = 0; ci < 3; ci++) {
            int c = (ci == 2) ? 3 : ci;
            float s = 0.0f;
            #pragma unroll
            for (int k = 0; k < 4; k++)
                s += K[r * 4 + k] * RT[k * 4 + c];
            g_P[m][r * 3 + ci] = s;
        }
    }
}

// One warp per BEV cell (b,i,j); lane == channel. All control flow warp-uniform.
__global__ __launch_bounds__(256) void ipm_kernel(const float* __restrict__ images,
                                                  float* __restrict__ out) {
    const int warp = (blockIdx.x * blockDim.x + threadIdx.x) >> 5;
    const int lane = threadIdx.x & 31;
    const int NCELL = NB * BEV_N * BEV_N;
    if (warp >= NCELL) return;

    const int b   = warp / (BEV_N * BEV_N);
    const int rem = warp - b * (BEV_N * BEV_N);
    const int i   = rem / BEV_N;
    const int j   = rem - i * BEV_N;

    // linspace(-50, 50, 200): match numpy's float64 evaluation, then round to fp32
    const float y = (float)(-50.0 + (double)i * (100.0 / 199.0));
    const float x = (float)(-50.0 + (double)j * (100.0 / 199.0));

    float best = -FLT_MAX;

    #pragma unroll
    for (int cam = 0; cam < NCAM; cam++) {
        const int bn = b * NCAM + cam;
        const float* P = g_P[bn];
        const float pc0 = P[0] * y + P[1] * x + P[2];
        const float pc1 = P[3] * y + P[4] * x + P[5];
        const float pc2 = P[6] * y + P[7] * x + P[8];
        const float inv = 1.0f / (pc2 + 1e-7f);
        const float fx = pc0 * inv;
        const float fy = pc1 * inv;

        float v = 0.0f;
        // Outside [0, W-1) x [0, H-1): clamped bilinear collapses => exactly 0
        if (fx >= 0.0f && fx < (float)(IMG_W - 1) &&
            fy >= 0.0f && fy < (float)(IMG_H - 1)) {
            const float x0f = floorf(fx);
            const float y0f = floorf(fy);
            const int x0 = (int)x0f;
            const int y0 = (int)y0f;
            const float wx1 = fx - x0f, wx0 = 1.0f - wx1;
            const float wy1 = fy - y0f, wy0 = 1.0f - wy1;

            const float* base = images
                + (((size_t)bn * IMG_H + y0) * IMG_W + x0) * NCH + lane;
            const float v00 = __ldg(base);
            const float v10 = __ldg(base + NCH);
            const float v01 = __ldg(base + (size_t)IMG_W * NCH);
            const float v11 = __ldg(base + (size_t)IMG_W * NCH + NCH);

            v = wx0 * wy0 * v00 + wx0 * wy1 * v01
              + wx1 * wy0 * v10 + wx1 * wy1 * v11;
        }
        best = fmaxf(best, v);
    }

    out[(size_t)warp * NCH + lane] = best;
}

extern "C" void kernel_launch(void* const* d_in, const int* in_sizes, int n_in,
                              void* d_out, int out_size) {
    const float* images = (const float*)d_in[0];
    const float* Ks     = (const float*)d_in[1];
    const float* RTs    = (const float*)d_in[2];
    float* out = (float*)d_out;

    precompute_P_kernel<<<1, BNMAT>>>(Ks, RTs);

    const int ncell = NB * BEV_N * BEV_N;        // 80,000 warps
    const int warps_per_block = 8;               // 256 threads
    const int nblocks = (ncell + warps_per_block - 1) / warps_per_block;
    ipm_kernel<<<nblocks, warps_per_block * 32>>>(images, out);
}

// round 3
// speedup vs baseline: 1.0069x; 1.0009x over previous
#include <cuda_runtime.h>
#include <float.h>
#include <math.h>

// Problem constants (from reference)
#define BEV_N   200          // BEV_H == BEV_W == 200
#define IMG_H   128
#define IMG_W   352
#define NCH     32
#define NB      2            // batch
#define NCAM    6            // cameras per batch
#define BNMAT   (NB*NCAM)    // 12 projection matrices

// Per-camera reduced projection: rows 0..2 of P=K@RT, columns {0(y),1(x),3(const)}
// (z column unused since plane z == 0)
__device__ float g_P[BNMAT][9];

__global__ void precompute_P_kernel(const float* __restrict__ Ks,
                                    const float* __restrict__ RTs) {
    int m = threadIdx.x;
    if (m >= BNMAT) return;
    const float* K  = Ks  + m * 16;
    const float* RT = RTs + m * 16;
    #pragma unroll
    for (int r = 0; r < 3; r++) {
        #pragma unroll
        for (int ci = 0; ci < 3; ci++) {
            int c = (ci == 2) ? 3 : ci;
            float s = 0.0f;
            #pragma unroll
            for (int k = 0; k < 4; k++)
                s += K[r * 4 + k] * RT[k * 4 + c];
            g_P[m][r * 3 + ci] = s;
        }
    }
}

// One warp per BEV cell (b,i,j); lane == channel. All control flow warp-uniform.
__global__ __launch_bounds__(256) void ipm_kernel(const float* __restrict__ images,
                                                  float* __restrict__ out) {
    const int warp = (blockIdx.x * blockDim.x + threadIdx.x) >> 5;
    const int lane = threadIdx.x & 31;
    const int NCELL = NB * BEV_N * BEV_N;
    if (warp >= NCELL) return;

    const int b   = warp / (BEV_N * BEV_N);
    const int rem = warp - b * (BEV_N * BEV_N);
    const int i   = rem / BEV_N;
    const int j   = rem - i * BEV_N;

    // linspace(-50, 50, 200): match numpy's float64 evaluation, then round to fp32
    const float y = (float)(-50.0 + (double)i * (100.0 / 199.0));
    const float x = (float)(-50.0 + (double)j * (100.0 / 199.0));

    float best = -FLT_MAX;

    #pragma unroll
    for (int cam = 0; cam < NCAM; cam++) {
        const int bn = b * NCAM + cam;
        const float* P = g_P[bn];
        const float pc0 = P[0] * y + P[1] * x + P[2];
        const float pc1 = P[3] * y + P[4] * x + P[5];
        const float pc2 = P[6] * y + P[7] * x + P[8];
        const float inv = 1.0f / (pc2 + 1e-7f);
        const float fx = pc0 * inv;
        const float fy = pc1 * inv;

        float v = 0.0f;
        // Outside [0, W-1) x [0, H-1): clamped bilinear collapses => exactly 0
        if (fx >= 0.0f && fx < (float)(IMG_W - 1) &&
            fy >= 0.0f && fy < (float)(IMG_H - 1)) {
            const float x0f = floorf(fx);
            const float y0f = floorf(fy);
            const int x0 = (int)x0f;
            const int y0 = (int)y0f;
            const float wx1 = fx - x0f, wx0 = 1.0f - wx1;
            const float wy1 = fy - y0f, wy0 = 1.0f - wy1;

            const float* base = images
                + (((size_t)bn * IMG_H + y0) * IMG_W + x0) * NCH + lane;
            const float v00 = __ldg(base);
            const float v10 = __ldg(base + NCH);
            const float v01 = __ldg(base + (size_t)IMG_W * NCH);
            const float v11 = __ldg(base + (size_t)IMG_W * NCH + NCH);

            v = wx0 * wy0 * v00 + wx0 * wy1 * v01
              + wx1 * wy0 * v10 + wx1 * wy1 * v11;
        }
        best = fmaxf(best, v);
    }

    out[(size_t)warp * NCH + lane] = best;
}

extern "C" void kernel_launch(void* const* d_in, const int* in_sizes, int n_in,
                              void* d_out, int out_size) {
    const float* images = (const float*)d_in[0];
    const float* Ks     = (const float*)d_in[1];
    const float* RTs    = (const float*)d_in[2];
    float* out = (float*)d_out;

    precompute_P_kernel<<<1, BNMAT>>>(Ks, RTs);

    const int ncell = NB * BEV_N * BEV_N;        // 80,000 warps
    const int warps_per_block = 8;               // 256 threads
    const int nblocks = (ncell + warps_per_block - 1) / warps_per_block;
    ipm_kernel<<<nblocks, warps_per_block * 32>>>(images, out);
}

// round 4
// speedup vs baseline: 1.9882x; 1.9746x over previous
#include <cuda_runtime.h>
#include <float.h>
#include <math.h>

// Problem constants (from reference)
#define BEV_N   200          // BEV_H == BEV_W == 200
#define IMG_H   128
#define IMG_W   352
#define NCH     32
#define NB      2            // batch
#define NCAM    6            // cameras per batch
#define BNMAT   (NB*NCAM)    // 12 projection matrices
#define NCELL   (NB*BEV_N*BEV_N)   // 80,000

// Per-camera reduced projection: rows 0..2 of P=K@RT, columns {0(y),1(x),3(const)}
// (z column unused since plane z == 0)
__device__ float g_P[BNMAT][9];

__global__ void precompute_P_kernel(const float* __restrict__ Ks,
                                    const float* __restrict__ RTs) {
    int m = threadIdx.x;
    if (m >= BNMAT) return;
    const float* K  = Ks  + m * 16;
    const float* RT = RTs + m * 16;
    #pragma unroll
    for (int r = 0; r < 3; r++) {
        #pragma unroll
        for (int ci = 0; ci < 3; ci++) {
            int c = (ci == 2) ? 3 : ci;
            float s = 0.0f;
            #pragma unroll
            for (int k = 0; k < 4; k++)
                s += K[r * 4 + k] * RT[k * 4 + c];
            g_P[m][r * 3 + ci] = s;
        }
    }
}

// 8 lanes per BEV cell; each lane owns 4 channels (float4). One warp = 4 cells.
__global__ __launch_bounds__(256) void ipm_kernel(const float* __restrict__ images,
                                                  float* __restrict__ out) {
    const int tid  = blockIdx.x * blockDim.x + threadIdx.x;
    const int cell = tid >> 3;          // BEV cell index
    const int sub  = tid & 7;           // channel group: channels [sub*4, sub*4+4)
    if (cell >= NCELL) return;

    const int b   = cell / (BEV_N * BEV_N);
    const int rem = cell - b * (BEV_N * BEV_N);
    const int i   = rem / BEV_N;
    const int j   = rem - i * BEV_N;

    // linspace(-50, 50, 200): match numpy's float64 evaluation, then round to fp32
    const float y = (float)(-50.0 + (double)i * (100.0 / 199.0));
    const float x = (float)(-50.0 + (double)j * (100.0 / 199.0));

    const float4* __restrict__ img4 = (const float4*)images;

    float4 best = make_float4(-FLT_MAX, -FLT_MAX, -FLT_MAX, -FLT_MAX);

    #pragma unroll
    for (int cam = 0; cam < NCAM; cam++) {
        const int bn = b * NCAM + cam;
        const float* P = g_P[bn];
        const float pc0 = P[0] * y + P[1] * x + P[2];
        const float pc1 = P[3] * y + P[4] * x + P[5];
        const float pc2 = P[6] * y + P[7] * x + P[8];
        const float inv = 1.0f / (pc2 + 1e-7f);
        const float fx = pc0 * inv;
        const float fy = pc1 * inv;

        float4 v = make_float4(0.f, 0.f, 0.f, 0.f);
        // Outside [0, W-1) x [0, H-1): clamped bilinear collapses => exactly 0
        if (fx >= 0.0f && fx < (float)(IMG_W - 1) &&
            fy >= 0.0f && fy < (float)(IMG_H - 1)) {
            const float x0f = floorf(fx);
            const float y0f = floorf(fy);
            const int x0 = (int)x0f;
            const int y0 = (int)y0f;
            const float wx1 = fx - x0f, wx0 = 1.0f - wx1;
            const float wy1 = fy - y0f, wy0 = 1.0f - wy1;

            // float4 index: 8 float4 per pixel (32 channels)
            const size_t base = (((size_t)bn * IMG_H + y0) * IMG_W + x0) * 8 + sub;
            const float4 v00 = __ldg(img4 + base);
            const float4 v10 = __ldg(img4 + base + 8);
            const float4 v01 = __ldg(img4 + base + (size_t)IMG_W * 8);
            const float4 v11 = __ldg(img4 + base + (size_t)IMG_W * 8 + 8);

            const float w00 = wx0 * wy0, w01 = wx0 * wy1;
            const float w10 = wx1 * wy0, w11 = wx1 * wy1;
            v.x = w00 * v00.x + w01 * v01.x + w10 * v10.x + w11 * v11.x;
            v.y = w00 * v00.y + w01 * v01.y + w10 * v10.y + w11 * v11.y;
            v.z = w00 * v00.z + w01 * v01.z + w10 * v10.z + w11 * v11.z;
            v.w = w00 * v00.w + w01 * v01.w + w10 * v10.w + w11 * v11.w;
        }
        best.x = fmaxf(best.x, v.x);
        best.y = fmaxf(best.y, v.y);
        best.z = fmaxf(best.z, v.z);
        best.w = fmaxf(best.w, v.w);
    }

    ((float4*)out)[(size_t)cell * 8 + sub] = best;
}

extern "C" void kernel_launch(void* const* d_in, const int* in_sizes, int n_in,
                              void* d_out, int out_size) {
    const float* images = (const float*)d_in[0];
    const float* Ks     = (const float*)d_in[1];
    const float* RTs    = (const float*)d_in[2];
    float* out = (float*)d_out;

    precompute_P_kernel<<<1, BNMAT>>>(Ks, RTs);

    const int nthreads = NCELL * 8;              // 8 lanes per cell
    const int block = 256;
    const int nblocks = (nthreads + block - 1) / block;
    ipm_kernel<<<nblocks, block>>>(images, out);
}

// round 5
// speedup vs baseline: 2.1963x; 1.1047x over previous
#include <cuda_runtime.h>
#include <float.h>
#include <math.h>

// Problem constants (from reference)
#define BEV_N   200          // BEV_H == BEV_W == 200
#define IMG_H   128
#define IMG_W   352
#define NCH     32
#define NB      2            // batch
#define NCAM    6            // cameras per batch
#define BNMAT   (NB*NCAM)    // 12 projection matrices
#define NCELL   (NB*BEV_N*BEV_N)   // 80,000
#define CELLS_PER_BLOCK 32   // 256 threads / 8 lanes-per-cell

// One fused kernel:
//  Phase 0: compute reduced P = (K@RT) rows 0..2, cols {0,1,3} into smem (z==0 plane)
//  Phase 1: one thread per (cell,cam); ballot-compact valid cams' {weights, base} to smem
//  Phase 2: 8 lanes per cell (float4 channels) sample only the valid cams
__global__ __launch_bounds__(256) void ipm_fused_kernel(const float* __restrict__ images,
                                                        const float* __restrict__ Ks,
                                                        const float* __restrict__ RTs,
                                                        float* __restrict__ out) {
    __shared__ float  sP[BNMAT][9];
    __shared__ float4 sW[CELLS_PER_BLOCK * NCAM];     // (w00,w01,w10,w11)
    __shared__ int    sBase[CELLS_PER_BLOCK * NCAM];  // float4-index of im00
    __shared__ int    sCnt[CELLS_PER_BLOCK];

    const int t = threadIdx.x;

    // ---------- Phase 0: projection matrices ----------
    if (t < BNMAT * 9) {
        const int m  = t / 9;
        const int e  = t - m * 9;
        const int r  = e / 3;
        const int ci = e - r * 3;
        const int c  = (ci == 2) ? 3 : ci;
        const float* K  = Ks  + m * 16 + r * 4;
        const float* RT = RTs + m * 16;
        sP[m][e] = K[0] * RT[c] + K[1] * RT[4 + c]
                 + K[2] * RT[8 + c] + K[3] * RT[12 + c];
    }
    __syncthreads();

    const int cell0 = blockIdx.x * CELLS_PER_BLOCK;   // grid is exactly 2500 blocks
    const int lc    = t >> 3;                          // local cell 0..31
    const int sub   = t & 7;                           // lane-in-cell / cam slot

    // ---------- Phase 1: project + compact valid cameras ----------
    {
        const int cam  = sub;                          // cams 0..5 active, 6..7 idle
        const int cell = cell0 + lc;
        bool valid = false;
        float4 w = make_float4(0.f, 0.f, 0.f, 0.f);
        int baseIdx = 0;

        if (cam < NCAM) {
            const int b   = cell / (BEV_N * BEV_N);
            const int rem = cell - b * (BEV_N * BEV_N);
            const int i   = rem / BEV_N;
            const int j   = rem - i * BEV_N;
            // linspace(-50,50,200) evaluated in float64 like numpy, rounded to fp32
            const float y = (float)(-50.0 + (double)i * (100.0 / 199.0));
            const float x = (float)(-50.0 + (double)j * (100.0 / 199.0));

            const int bn = b * NCAM + cam;
            const float* P = sP[bn];
            const float pc0 = P[0] * y + P[1] * x + P[2];
            const float pc1 = P[3] * y + P[4] * x + P[5];
            const float pc2 = P[6] * y + P[7] * x + P[8];
            const float inv = 1.0f / (pc2 + 1e-7f);
            const float fx = pc0 * inv;
            const float fy = pc1 * inv;

            // Outside [0,W-1) x [0,H-1): clamped bilinear collapses => exact 0
            if (fx >= 0.0f && fx < (float)(IMG_W - 1) &&
                fy >= 0.0f && fy < (float)(IMG_H - 1)) {
                valid = true;
                const float x0f = floorf(fx);
                const float y0f = floorf(fy);
                const float wx1 = fx - x0f, wx0 = 1.0f - wx1;
                const float wy1 = fy - y0f, wy0 = 1.0f - wy1;
                w = make_float4(wx0 * wy0, wx0 * wy1, wx1 * wy0, wx1 * wy1);
                baseIdx = (((int)(bn * IMG_H) + (int)y0f) * IMG_W + (int)x0f) * (NCH / 4);
            }
        }

        const unsigned ball = __ballot_sync(0xFFFFFFFFu, valid);
        const int laneBase  = (t & 31) & ~7;                      // first lane of 8-group
        const unsigned grp  = (ball >> laneBase) & 0xFFu;
        if (valid) {
            const int slot = __popc(grp & ((1u << sub) - 1u));    // cam-ordered slot
            sW[lc * NCAM + slot]    = w;
            sBase[lc * NCAM + slot] = baseIdx;
        }
        if (cam == 0) sCnt[lc] = (int)__popc(grp);
    }
    __syncthreads();

    // ---------- Phase 2: sample valid cams, max-reduce ----------
    const int n = sCnt[lc];
    // If every cam is valid, result is max over the 6 samples; otherwise some cam
    // contributes an exact 0 (clamp-collapsed weights), so seed with 0.
    float4 best = (n == NCAM)
        ? make_float4(-FLT_MAX, -FLT_MAX, -FLT_MAX, -FLT_MAX)
        : make_float4(0.f, 0.f, 0.f, 0.f);

    const float4* __restrict__ img4 = (const float4*)images;
    const int rowStride = IMG_W * (NCH / 4);

    for (int k = 0; k < n; k++) {
        const float4 w   = sW[lc * NCAM + k];
        const int   base = sBase[lc * NCAM + k] + sub;
        const float4 v00 = __ldg(img4 + base);
        const float4 v10 = __ldg(img4 + base + (NCH / 4));
        const float4 v01 = __ldg(img4 + base + rowStride);
        const float4 v11 = __ldg(img4 + base + rowStride + (NCH / 4));

        float4 v;
        v.x = w.x * v00.x + w.y * v01.x + w.z * v10.x + w.w * v11.x;
        v.y = w.x * v00.y + w.y * v01.y + w.z * v10.y + w.w * v11.y;
        v.z = w.x * v00.z + w.y * v01.z + w.z * v10.z + w.w * v11.z;
        v.w = w.x * v00.w + w.y * v01.w + w.z * v10.w + w.w * v11.w;

        best.x = fmaxf(best.x, v.x);
        best.y = fmaxf(best.y, v.y);
        best.z = fmaxf(best.z, v.z);
        best.w = fmaxf(best.w, v.w);
    }

    ((float4*)out)[(size_t)(cell0 + lc) * (NCH / 4) + sub] = best;
}

extern "C" void kernel_launch(void* const* d_in, const int* in_sizes, int n_in,
                              void* d_out, int out_size) {
    const float* images = (const float*)d_in[0];
    const float* Ks     = (const float*)d_in[1];
    const float* RTs    = (const float*)d_in[2];
    float* out = (float*)d_out;

    const int nblocks = NCELL / CELLS_PER_BLOCK;   // 80000/32 = 2500, exact
    ipm_fused_kernel<<<nblocks, 256>>>(images, Ks, RTs, out);
}